// round 7
// baseline (speedup 1.0000x reference)
#include <cuda_runtime.h>
#include <math.h>
#include <stdint.h>

// Problem: B=4, S=4096, D=2048, E=64, K=2
#define M_TOKENS 16384
#define D_DIM    2048
#define E_EXP    64
#define TM       128
#define NCTA     (M_TOKENS / TM)       // 128
#define NTHREADS 256

// K split: tensor warps (0-3) cover [0,KT); fma2 warps (4-7) cover [KT,2048)
#define KT       768
#define NCHT     (KT / 16)             // 48 tensor chunks of k16
#define KF       (D_DIM - KT)          // 1280
#define NCHF     (KF / 32)             // 40 fma2 chunks of k32

// Tensor smem: x [128 x 20f], W [64 x 20f] per stage, 3 stages
#define T_X_FLOATS (128 * 20)
#define T_STAGE    ((T_X_FLOATS + 64 * 20) * 4)   // 15360
#define T_SMEM     (3 * T_STAGE)                   // 46080
// fma2 smem: x [128 x 36f], W [32k x 16 granules x 16B] per stage, 2 stages
#define F_X_BYTES  (128 * 36 * 4)                  // 18432
#define F_STAGE    (F_X_BYTES + 32 * 16 * 16)      // 26624
#define DYN_BYTES  (T_SMEM + 2 * F_STAGE)          // 99328

__device__ float g_partials[NCTA * 128];
// W transposed for fma2 range: [k-768][granule(16B = 4 experts)]
__device__ __align__(16) float g_wt[KF * E_EXP];

#define CP16(smem_a, gptr) \
    asm volatile("cp.async.cg.shared.global [%0], [%1], 16;" \
                 :: "r"(smem_a), "l"(gptr) : "memory")
#define CP_COMMIT() asm volatile("cp.async.commit_group;" ::: "memory")
#define CP_WAIT1()  asm volatile("cp.async.wait_group 1;" ::: "memory")
#define BAR(id)     asm volatile("bar.sync %0, 128;" :: "r"(id) : "memory")

static __device__ __forceinline__ uint32_t smem_u32(const void* p) {
    uint32_t r;
    asm("{ .reg .u64 t; cvta.to.shared.u64 t, %1; cvt.u32.u64 %0, t; }"
        : "=r"(r) : "l"(p));
    return r;
}
static __device__ __forceinline__ void fma2(uint64_t& acc, uint64_t a, uint64_t b) {
    asm("fma.rn.f32x2 %0, %1, %2, %0;" : "+l"(acc) : "l"(a), "l"(b));
}
static __device__ __forceinline__ uint64_t dup2(float v) {
    uint64_t r;
    asm("mov.b64 %0, {%1, %1};" : "=l"(r) : "f"(v));
    return r;
}
static __device__ __forceinline__ void lds_v2u64(uint64_t& a, uint64_t& b, uint32_t addr) {
    asm volatile("ld.shared.v2.u64 {%0, %1}, [%2];" : "=l"(a), "=l"(b) : "r"(addr));
}
static __device__ __forceinline__ void mma_tf32(float* d,
        uint32_t a0, uint32_t a1, uint32_t a2, uint32_t a3,
        uint32_t b0, uint32_t b1) {
    asm volatile(
        "mma.sync.aligned.m16n8k8.row.col.f32.tf32.tf32.f32 "
        "{%0,%1,%2,%3},{%4,%5,%6,%7},{%8,%9},{%0,%1,%2,%3};"
        : "+f"(d[0]), "+f"(d[1]), "+f"(d[2]), "+f"(d[3])
        : "r"(a0), "r"(a1), "r"(a2), "r"(a3), "r"(b0), "r"(b1));
}
static __device__ __forceinline__ void split1(float v, uint32_t& hi, uint32_t& lo) {
    uint32_t uv = __float_as_uint(v);
    hi = uv & 0xFFFFE000u;
    lo = __float_as_uint(v - __uint_as_float(hi));
}

// pre-kernel: W-transpose image for k in [KT, 2048), plain layout
__global__ void wt_kernel(const float* __restrict__ W)
{
    int g = blockIdx.x * blockDim.x + threadIdx.x;   // 0..20479
    int kp = g >> 4;
    int q  = g & 15;
    int k  = KT + kp;
    float4 v;
    v.x = W[(size_t)(4 * q + 0) * D_DIM + k];
    v.y = W[(size_t)(4 * q + 1) * D_DIM + k];
    v.z = W[(size_t)(4 * q + 2) * D_DIM + k];
    v.w = W[(size_t)(4 * q + 3) * D_DIM + k];
    *reinterpret_cast<float4*>(&g_wt[(size_t)g * 4]) = v;
}

__global__ __launch_bounds__(NTHREADS, 1)
void router_hybrid(const float* __restrict__ x, const float* __restrict__ W,
                   float* __restrict__ out)
{
    extern __shared__ __align__(16) char dsm[];
    __shared__ int tops[TM][2];

    const int tid  = threadIdx.x;
    const int wid  = tid >> 5;
    const int lane = tid & 31;
    const int cta  = blockIdx.x;
    const size_t tbase = (size_t)cta * TM;
    const uint32_t sb0 = smem_u32(dsm);

    float* probs = reinterpret_cast<float*>(dsm);   // epilogue overlay [128][66]

    if (wid < 4) {
        // ================= TENSOR PATH: k in [0, KT) =================
        const int w  = wid;
        const int qr = lane >> 2, qc = lane & 3;
        const int tidT = tid;                        // 0..127

        auto load_t = [&](int c, int s) {
            const int k0 = c * 16;
            const uint32_t bs = sb0 + (uint32_t)s * T_STAGE;
#pragma unroll
            for (int p = 0; p < 4; p++) {            // x: 512 segs
                int seg = tidT + p * 128;
                int row = seg >> 2, c4 = (seg & 3) << 2;
                const float* g = x + (tbase + row) * (size_t)D_DIM + k0 + c4;
                CP16(bs + (uint32_t)(row * 20 + c4) * 4, g);
            }
#pragma unroll
            for (int p = 0; p < 2; p++) {            // W: 256 segs
                int seg = tidT + p * 128;
                int row = seg >> 2, c4 = (seg & 3) << 2;
                const float* g = W + (size_t)row * D_DIM + k0 + c4;
                CP16(bs + (uint32_t)T_X_FLOATS * 4 + (uint32_t)(row * 20 + c4) * 4, g);
            }
        };

        float acc[2][8][4];
#pragma unroll
        for (int mb = 0; mb < 2; mb++)
#pragma unroll
            for (int n = 0; n < 8; n++)
#pragma unroll
                for (int j = 0; j < 4; j++) acc[mb][n][j] = 0.0f;

        load_t(0, 0); CP_COMMIT();
        load_t(1, 1); CP_COMMIT();

        for (int c = 0; c < NCHT; c++) {
            CP_WAIT1();
            BAR(1);
            if (c + 2 < NCHT) load_t(c + 2, (c + 2) % 3);
            CP_COMMIT();

            const float* xs = reinterpret_cast<const float*>(dsm + (c % 3) * T_STAGE);
            const float* ws = xs + T_X_FLOATS;
#pragma unroll
            for (int kk = 0; kk < 16; kk += 8) {
                const int kc = kk + qc;
                uint32_t ah[2][4], al[2][4];
#pragma unroll
                for (int mb = 0; mb < 2; mb++) {
                    const int ar = (w * 32 + mb * 16 + qr) * 20;
                    split1(xs[ar + kc],           ah[mb][0], al[mb][0]);
                    split1(xs[ar + 160 + kc],     ah[mb][1], al[mb][1]);
                    split1(xs[ar + kc + 4],       ah[mb][2], al[mb][2]);
                    split1(xs[ar + 160 + kc + 4], ah[mb][3], al[mb][3]);
                }
#pragma unroll
                for (int n = 0; n < 8; n++) {
                    uint32_t bh0, bl0, bh1, bl1;
                    split1(ws[(n * 8 + qr) * 20 + kc],     bh0, bl0);
                    split1(ws[(n * 8 + qr) * 20 + kc + 4], bh1, bl1);
#pragma unroll
                    for (int mb = 0; mb < 2; mb++) {
                        mma_tf32(acc[mb][n], ah[mb][0], ah[mb][1], ah[mb][2], ah[mb][3], bh0, bh1);
                        mma_tf32(acc[mb][n], ah[mb][0], ah[mb][1], ah[mb][2], ah[mb][3], bl0, bl1);
                        mma_tf32(acc[mb][n], al[mb][0], al[mb][1], al[mb][2], al[mb][3], bh0, bh1);
                    }
                }
            }
        }
        BAR(1);   // all tensor warps done before overlay store

        // store tensor partial logits into probs overlay
#pragma unroll
        for (int mb = 0; mb < 2; mb++) {
            const int tr0 = w * 32 + mb * 16 + qr;
#pragma unroll
            for (int n = 0; n < 8; n++) {
                const int cb = n * 8 + qc * 2;
                *reinterpret_cast<float2*>(&probs[tr0 * 66 + cb]) =
                    make_float2(acc[mb][n][0], acc[mb][n][1]);
                *reinterpret_cast<float2*>(&probs[(tr0 + 8) * 66 + cb]) =
                    make_float2(acc[mb][n][2], acc[mb][n][3]);
            }
        }
    } else {
        // ================= FMA2 PATH: k in [KT, 2048) =================
        const int tid2 = tid - 128;                  // 0..127
        const int row  = tid2 >> 2;                  // 0..31
        const int col  = tid2 & 3;                   // granules 4col..4col+3

        auto load_f = [&](int c, int s) {
            const int k0 = KT + c * 32;
            const uint32_t bs = sb0 + (uint32_t)(T_SMEM + s * F_STAGE);
#pragma unroll
            for (int p = 0; p < 8; p++) {            // x: 1024 segs
                int seg = tid2 + p * 128;
                int t = seg >> 3, sk = seg & 7;
                const float* g = x + (tbase + t) * (size_t)D_DIM + k0 + sk * 4;
                CP16(bs + (uint32_t)(t * 36 + sk * 4) * 4, g);
            }
#pragma unroll
            for (int p = 0; p < 4; p++) {            // W image: 512 granules
                int seg = tid2 + p * 128;
                const float* g = g_wt + (size_t)(c * 512 + seg) * 4;
                CP16(bs + (uint32_t)F_X_BYTES + (uint32_t)seg * 16, g);
            }
        };

        uint64_t acc[4][8];                          // [token j][pair p]
#pragma unroll
        for (int j = 0; j < 4; j++)
#pragma unroll
            for (int p = 0; p < 8; p++) acc[j][p] = 0ull;

        load_f(0, 0); CP_COMMIT();
        load_f(1, 1); CP_COMMIT();

        for (int c = 0; c < NCHF; c++) {
            CP_WAIT1();
            BAR(2);

            const int s = c & 1;
            const float* xs =
                reinterpret_cast<const float*>(dsm + T_SMEM + s * F_STAGE);
            const uint32_t wsu = sb0 + (uint32_t)(T_SMEM + s * F_STAGE + F_X_BYTES);

#pragma unroll 2
            for (int kk = 0; kk < 32; kk += 4) {
                float4 xv[4];
#pragma unroll
                for (int j = 0; j < 4; j++)
                    xv[j] = *reinterpret_cast<const float4*>(
                        &xs[(row + 32 * j) * 36 + kk]);
#pragma unroll
                for (int dk = 0; dk < 4; dk++) {
                    uint64_t b[8];
                    const uint32_t kb = wsu + (uint32_t)(kk + dk) * 256 + col * 64;
                    lds_v2u64(b[0], b[1], kb);
                    lds_v2u64(b[2], b[3], kb + 16);
                    lds_v2u64(b[4], b[5], kb + 32);
                    lds_v2u64(b[6], b[7], kb + 48);
#pragma unroll
                    for (int j = 0; j < 4; j++) {
                        float xf = (dk == 0) ? xv[j].x : (dk == 1) ? xv[j].y
                                 : (dk == 2) ? xv[j].z : xv[j].w;
                        uint64_t xx = dup2(xf);
#pragma unroll
                        for (int p = 0; p < 8; p++) fma2(acc[j][p], xx, b[p]);
                    }
                }
            }
            BAR(2);
            if (c + 2 < NCHF) load_f(c + 2, s);
            CP_COMMIT();
        }

        // stash accs until after the full barrier (adds happen below)
        __syncthreads();   // joins with tensor path's barrier below

        // add fma2 partials into probs
#pragma unroll
        for (int j = 0; j < 4; j++) {
            const int t = row + 32 * j;
#pragma unroll
            for (int p = 0; p < 8; p++) {
                float lo = __uint_as_float((uint32_t)acc[j][p]);
                float hi = __uint_as_float((uint32_t)(acc[j][p] >> 32));
                float2* dst = reinterpret_cast<float2*>(
                    &probs[t * 66 + col * 16 + p * 2]);
                float2 v = *dst;
                v.x += lo; v.y += hi;
                *dst = v;
            }
        }
    }

    // Tensor path arrives here after its overlay store; fma2 path executed the
    // matching __syncthreads above. Keep barrier counts equal across paths.
    if (wid < 4) __syncthreads();

    __syncthreads();   // fma2 adds complete; logits final

    // one thread per token: softmax + top-2 + gates + outputs
    if (tid < TM) {
        const int t = tid;
        float f[64];
#pragma unroll
        for (int e = 0; e < E_EXP; e++) f[e] = probs[t * 66 + e];
        float mx = f[0];
#pragma unroll
        for (int e = 1; e < E_EXP; e++) mx = fmaxf(mx, f[e]);
        float S = 0.0f, b1 = -1.0f, b2 = -1.0f;
        int i1 = 0, i2 = 0;
#pragma unroll
        for (int e = 0; e < E_EXP; e++) {
            float v = expf(f[e] - mx);
            f[e] = v;
            S += v;
            if (v > b1) { b2 = b1; i2 = i1; b1 = v; i1 = e; }
            else if (v > b2) { b2 = v; i2 = e; }
        }
        const float invS = 1.0f / S;
#pragma unroll
        for (int e = 0; e < E_EXP; e++) probs[t * 66 + e] = f[e] * invS;
        tops[t][0] = i1;
        tops[t][1] = i2;

        const float p1 = b1 * invS, p2 = b2 * invS;
        const float denom = p1 + p2 + 1e-9f;
        const size_t gt = tbase + t;
        out[gt * 2 + 0] = (float)i1;
        out[gt * 2 + 1] = (float)i2;
        out[(size_t)M_TOKENS * 2 + gt * 2 + 0] = p1 / denom;
        out[(size_t)M_TOKENS * 2 + gt * 2 + 1] = p2 / denom;
    }
    __syncthreads();

    if (tid < E_EXP) {
        const int e = tid;
        float cnt = 0.0f, sp = 0.0f;
#pragma unroll 4
        for (int t = 0; t < TM; t++) {
            sp  += probs[t * 66 + e];
            cnt += (float)((tops[t][0] == e) + (tops[t][1] == e));
        }
        g_partials[cta * 128 + e]      = cnt;
        g_partials[cta * 128 + 64 + e] = sp;
    }
}

__global__ void aux_kernel2(float* __restrict__ out)
{
    __shared__ float sC[16][64];
    __shared__ float sP[16][64];
    __shared__ float red[64];
    const int t = threadIdx.x;          // 1024 threads
    const int c = t >> 6, e = t & 63;
    float C = 0.0f, P = 0.0f;
#pragma unroll
    for (int j = 0; j < 8; j++) {
        const int b = c + 16 * j;
        C += g_partials[b * 128 + e];
        P += g_partials[b * 128 + 64 + e];
    }
    sC[c][e] = C; sP[c][e] = P;
    __syncthreads();
    if (t < 64) {
        float Ct = 0.0f, Pt = 0.0f;
#pragma unroll
        for (int j = 0; j < 16; j++) { Ct += sC[j][t]; Pt += sP[j][t]; }
        red[t] = Ct * Pt;
    }
    __syncthreads();
#pragma unroll
    for (int s = 32; s > 0; s >>= 1) {
        if (t < s) red[t] += red[t + s];
        __syncthreads();
    }
    if (t == 0)
        out[(size_t)M_TOKENS * 4] =
            0.01f * 64.0f * red[0] / (32768.0f * 16384.0f);
}

extern "C" void kernel_launch(void* const* d_in, const int* in_sizes, int n_in,
                              void* d_out, int out_size)
{
    const float* x = (const float*)d_in[0];   // [4,4096,2048] f32
    const float* W = (const float*)d_in[1];   // [64,2048] f32
    float* out = (float*)d_out;               // [32768 idx | 32768 gates | 1 aux]

    cudaFuncSetAttribute(router_hybrid,
                         cudaFuncAttributeMaxDynamicSharedMemorySize, DYN_BYTES);

    wt_kernel<<<(KF * 16) / 256, 256>>>(W);
    router_hybrid<<<NCTA, NTHREADS, DYN_BYTES>>>(x, W, out);
    aux_kernel2<<<1, 1024>>>(out);
}